// round 4
// baseline (speedup 1.0000x reference)
#include <cuda_runtime.h>
#include <cuda_bf16.h>
#include <cstdint>
#include <cstddef>

// ---------------------------------------------------------------------------
#define BB 8
#define CC 256
#define SS 1024
#define NH 8
#define DK 256
#define HD 2048
#define QKVN 6144

#define BM 128
#define BN 128
#define BKF 32            // K elements per block
#define PAD 40            // bf16 per smem row (80B; conflict-free for ldmatrix)
#define TILEB (128 * PAD * 2)          // bytes per tile (10240)
#define STAGEB (4 * TILEB)             // A_h, A_l, B_h, B_l
#define NSTAGE 3
#define SMEM_DYN (NSTAGE * STAGEB)     // 120 KB

typedef __nv_bfloat16 bf16;
typedef __nv_bfloat162 bf162;

// ---------------------------------------------------------------------------
// Device scratch (allocation-free)
// ---------------------------------------------------------------------------
__device__ __align__(128) bf16 g_xt_h[BB * SS * CC],  g_xt_l[BB * SS * CC];
__device__ __align__(128) bf16 g_WpT_h[QKVN * CC],    g_WpT_l[QKVN * CC];
__device__ __align__(128) bf16 g_WoT_h[CC * HD],      g_WoT_l[CC * HD];
__device__ __align__(128) bf16 g_q_h[BB * NH * SS * DK], g_q_l[BB * NH * SS * DK];
__device__ __align__(128) bf16 g_k_h[BB * NH * SS * DK], g_k_l[BB * NH * SS * DK];
__device__ __align__(128) bf16 g_v_h[BB * NH * SS * DK], g_v_l[BB * NH * SS * DK];
__device__ __align__(128) bf16 g_vt_h[BB * NH * DK * SS], g_vt_l[BB * NH * DK * SS];
__device__ __align__(128) float g_scores[(size_t)BB * NH * SS * SS];
__device__ __align__(128) bf16 g_p_h[(size_t)BB * NH * SS * SS];
__device__ __align__(128) bf16 g_p_l[(size_t)BB * NH * SS * SS];
__device__ __align__(128) bf16 g_ao_h[BB * SS * HD],  g_ao_l[BB * SS * HD];

// ---------------------------------------------------------------------------
// PTX helpers (portable at compute_103 baseline: sm_80-era features only)
// ---------------------------------------------------------------------------
__device__ __forceinline__ uint32_t smem_u32(const void* p) {
    uint32_t a;
    asm("{ .reg .u64 t; cvta.to.shared.u64 t, %1; cvt.u32.u64 %0, t; }"
        : "=r"(a) : "l"(p));
    return a;
}
__device__ __forceinline__ void cpa16(uint32_t dst, const void* src) {
    asm volatile("cp.async.cg.shared.global [%0], [%1], 16;"
                 :: "r"(dst), "l"(src) : "memory");
}
__device__ __forceinline__ void cpa_commit() {
    asm volatile("cp.async.commit_group;" ::: "memory");
}
template <int N> __device__ __forceinline__ void cpa_wait() {
    asm volatile("cp.async.wait_group %0;" :: "n"(N) : "memory");
}
__device__ __forceinline__ void ldsm4(uint32_t* r, uint32_t addr) {
    asm volatile("ldmatrix.sync.aligned.m8n8.x4.shared.b16 {%0,%1,%2,%3}, [%4];"
                 : "=r"(r[0]), "=r"(r[1]), "=r"(r[2]), "=r"(r[3]) : "r"(addr));
}
__device__ __forceinline__ void mma16816(float* d, const uint32_t* a,
                                         uint32_t b0, uint32_t b1) {
    asm volatile(
        "mma.sync.aligned.m16n8k16.row.col.f32.bf16.bf16.f32 "
        "{%0,%1,%2,%3}, {%4,%5,%6,%7}, {%8,%9}, {%0,%1,%2,%3};"
        : "+f"(d[0]), "+f"(d[1]), "+f"(d[2]), "+f"(d[3])
        : "r"(a[0]), "r"(a[1]), "r"(a[2]), "r"(a[3]), "r"(b0), "r"(b1));
}
__device__ __forceinline__ void split2(float v, bf16& h, bf16& l) {
    h = __float2bfloat16(v);
    l = __float2bfloat16(v - __bfloat162float(h));
}

// ---------------------------------------------------------------------------
// fp32 [Z][R][C] -> transposed split bf16 [Z][C][R] (hi, lo)
// ---------------------------------------------------------------------------
__global__ __launch_bounds__(256) void convT(const float* __restrict__ in,
                                             bf16* __restrict__ oh,
                                             bf16* __restrict__ ol, int R, int C) {
    __shared__ float t[32][33];
    int z = blockIdx.z;
    const float* I = in + (size_t)z * R * C;
    size_t ob = (size_t)z * R * C;
    int c0 = blockIdx.x * 32, r0 = blockIdx.y * 32;
    int x = threadIdx.x, y = threadIdx.y;
#pragma unroll
    for (int i = 0; i < 32; i += 8)
        t[y + i][x] = I[(size_t)(r0 + y + i) * C + c0 + x];
    __syncthreads();
#pragma unroll
    for (int i = 0; i < 32; i += 8) {
        float v = t[x][y + i];
        bf16 h, l; split2(v, h, l);
        size_t idx = ob + (size_t)(c0 + y + i) * R + r0 + x;
        oh[idx] = h; ol[idx] = l;
    }
}

// ---------------------------------------------------------------------------
// bf16 pair transpose: [Z][R][C] -> [Z][C][R] for hi & lo arrays
// ---------------------------------------------------------------------------
__global__ __launch_bounds__(256) void txpb2(const bf16* __restrict__ ih,
                                             const bf16* __restrict__ il,
                                             bf16* __restrict__ oh,
                                             bf16* __restrict__ ol, int R, int C) {
    __shared__ bf16 th[32][33], tl[32][33];
    int z = blockIdx.z;
    size_t zb = (size_t)z * R * C;
    int c0 = blockIdx.x * 32, r0 = blockIdx.y * 32;
    int x = threadIdx.x, y = threadIdx.y;
#pragma unroll
    for (int i = 0; i < 32; i += 8) {
        size_t idx = zb + (size_t)(r0 + y + i) * C + c0 + x;
        th[y + i][x] = ih[idx];
        tl[y + i][x] = il[idx];
    }
    __syncthreads();
#pragma unroll
    for (int i = 0; i < 32; i += 8) {
        size_t idx = zb + (size_t)(c0 + y + i) * R + r0 + x;
        oh[idx] = th[x][y + i];
        ol[idx] = tl[x][y + i];
    }
}

// ---------------------------------------------------------------------------
// bf16x3 GEMM, cp.async 3-stage pipeline. C tile = A[128,K] * B[128,K]^T
// MODE 0: QKV   -> bias, split-scatter to q/k/v (hi/lo)
// MODE 1: QK^T  -> scale, fp32 scores
// MODE 2: PV    -> split store to attnout (hi/lo)
// MODE 3: proj  -> bias + residual + transposed fp32 store
// ---------------------------------------------------------------------------
template <int MODE>
__global__ __launch_bounds__(256) void gemm_bf16x3(
    const bf16* __restrict__ Ah, const bf16* __restrict__ Al,
    const bf16* __restrict__ Bh, const bf16* __restrict__ Bl,
    float* __restrict__ C, bf16* __restrict__ Ch, bf16* __restrict__ Cl,
    int K, int ldA, int ldB, int ldC, size_t Az, size_t Bz, size_t Cz,
    const float* __restrict__ bias, const float* __restrict__ resid, float scale) {
    extern __shared__ __align__(16) char dynsm[];
    const uint32_t sbase = smem_u32(dynsm);

    const int tid = threadIdx.x;
    const int wid = tid >> 5;
    const int lane = tid & 31;
    const int wr = wid >> 1;
    const int wc = wid & 1;

    const int z = blockIdx.z;
    const int m0 = blockIdx.y * BM;
    const int n0 = blockIdx.x * BN;
    const bf16* tA_h = Ah + Az * z + (size_t)m0 * ldA;
    const bf16* tA_l = Al + Az * z + (size_t)m0 * ldA;
    const bf16* tB_h = Bh + Bz * z + (size_t)n0 * ldB;
    const bf16* tB_l = Bl + Bz * z + (size_t)n0 * ldB;
    const int NKB = K / BKF;

    // cp.async mapping: row = tid>>1 (0..127), half = tid&1 (two 16B chunks)
    const int crow = tid >> 1;
    const int chalf = tid & 1;

    auto issue = [&](int kb, int stg) {
        const bf16* srcs[4] = {tA_h, tA_l, tB_h, tB_l};
        const int lds[4] = {ldA, ldA, ldB, ldB};
        uint32_t sb = sbase + stg * STAGEB + (crow * PAD + chalf * 16) * 2;
#pragma unroll
        for (int t = 0; t < 4; ++t) {
            const bf16* g = srcs[t] + (size_t)crow * lds[t] + kb * BKF + chalf * 16;
            uint32_t d = sb + t * TILEB;
            cpa16(d, g);
            cpa16(d + 16, g + 8);
        }
    };

    // ldmatrix per-lane offsets
    const int lr = lane & 15, lhf = lane >> 4;
    uint32_t aoff[2], boff[4];
#pragma unroll
    for (int im = 0; im < 2; ++im)
        aoff[im] = ((wr * 32 + im * 16 + lr) * PAD + lhf * 8) * 2;
#pragma unroll
    for (int jn = 0; jn < 4; ++jn)
        boff[jn] = ((wc * 64 + jn * 16 + lr) * PAD + lhf * 8) * 2;

    float acc[2][8][4] = {};

    issue(0, 0); cpa_commit();
    if (NKB > 1) { issue(1, 1); cpa_commit(); }

    for (int kb = 0; kb < NKB; ++kb) {
        const int stg = kb % NSTAGE;
        if (kb + 2 < NKB) { issue(kb + 2, (kb + 2) % NSTAGE); cpa_commit(); }
        if (kb + 2 < NKB) cpa_wait<2>();
        else if (kb + 1 < NKB) cpa_wait<1>();
        else cpa_wait<0>();
        __syncthreads();

        const uint32_t sA_h = sbase + stg * STAGEB;
        const uint32_t sA_l = sA_h + TILEB;
        const uint32_t sB_h = sA_h + 2 * TILEB;
        const uint32_t sB_l = sA_h + 3 * TILEB;

#pragma unroll
        for (int ks = 0; ks < 32; ks += 16) {
            const uint32_t kso = ks * 2;
            uint32_t ah[2][4], axl[2][4], bbf[4][4];
            ldsm4(ah[0], sA_h + aoff[0] + kso);
            ldsm4(ah[1], sA_h + aoff[1] + kso);
#pragma unroll
            for (int jn = 0; jn < 4; ++jn) ldsm4(bbf[jn], sB_h + boff[jn] + kso);
#pragma unroll
            for (int im = 0; im < 2; ++im)
#pragma unroll
                for (int jn = 0; jn < 4; ++jn) {
                    mma16816(acc[im][jn * 2], ah[im], bbf[jn][0], bbf[jn][2]);
                    mma16816(acc[im][jn * 2 + 1], ah[im], bbf[jn][1], bbf[jn][3]);
                }
            ldsm4(axl[0], sA_l + aoff[0] + kso);
            ldsm4(axl[1], sA_l + aoff[1] + kso);
#pragma unroll
            for (int im = 0; im < 2; ++im)
#pragma unroll
                for (int jn = 0; jn < 4; ++jn) {
                    mma16816(acc[im][jn * 2], axl[im], bbf[jn][0], bbf[jn][2]);
                    mma16816(acc[im][jn * 2 + 1], axl[im], bbf[jn][1], bbf[jn][3]);
                }
#pragma unroll
            for (int jn = 0; jn < 4; ++jn) ldsm4(bbf[jn], sB_l + boff[jn] + kso);
#pragma unroll
            for (int im = 0; im < 2; ++im)
#pragma unroll
                for (int jn = 0; jn < 4; ++jn) {
                    mma16816(acc[im][jn * 2], ah[im], bbf[jn][0], bbf[jn][2]);
                    mma16816(acc[im][jn * 2 + 1], ah[im], bbf[jn][1], bbf[jn][3]);
                }
        }
        __syncthreads();
    }

    // ---- epilogue ----
    const int r0l = lane >> 2;
    const int c0l = (lane & 3) * 2;

    if (MODE == 0) {
        const int hB = n0 / 768;
        const int loc0 = n0 % 768;
        const int seg = loc0 >> 8;
        const int d0 = loc0 & 255;
        bf16* dh = (seg == 0) ? g_q_h : (seg == 1) ? g_k_h : g_v_h;
        bf16* dl = (seg == 0) ? g_q_l : (seg == 1) ? g_k_l : g_v_l;
#pragma unroll
        for (int im = 0; im < 2; ++im)
#pragma unroll
            for (int jn = 0; jn < 8; ++jn)
#pragma unroll
                for (int p = 0; p < 2; ++p) {
                    int m = m0 + wr * 32 + im * 16 + r0l + p * 8;
                    int nb = wc * 64 + jn * 8 + c0l;
                    int b = m >> 10, s2 = m & 1023;
                    size_t row = ((size_t)(b * NH + hB) * SS + s2) * DK + d0 + nb;
                    float v0 = acc[im][jn][p * 2] + bias[n0 + nb];
                    float v1 = acc[im][jn][p * 2 + 1] + bias[n0 + nb + 1];
                    bf162 h, l;
                    split2(v0, h.x, l.x);
                    split2(v1, h.y, l.y);
                    *(bf162*)(dh + row) = h;
                    *(bf162*)(dl + row) = l;
                }
    } else if (MODE == 1) {
        float* Cb = C + Cz * z;
#pragma unroll
        for (int im = 0; im < 2; ++im)
#pragma unroll
            for (int jn = 0; jn < 8; ++jn)
#pragma unroll
                for (int p = 0; p < 2; ++p) {
                    int m = m0 + wr * 32 + im * 16 + r0l + p * 8;
                    int nb = wc * 64 + jn * 8 + c0l;
                    float2 o;
                    o.x = acc[im][jn][p * 2] * scale;
                    o.y = acc[im][jn][p * 2 + 1] * scale;
                    *(float2*)(Cb + (size_t)m * ldC + n0 + nb) = o;
                }
    } else if (MODE == 2) {
        int b = z >> 3, h2 = z & 7;
        size_t base = (size_t)b * SS * HD + h2 * DK;
#pragma unroll
        for (int im = 0; im < 2; ++im)
#pragma unroll
            for (int jn = 0; jn < 8; ++jn)
#pragma unroll
                for (int p = 0; p < 2; ++p) {
                    int m = m0 + wr * 32 + im * 16 + r0l + p * 8;
                    int nb = wc * 64 + jn * 8 + c0l;
                    size_t idx = base + (size_t)m * HD + n0 + nb;
                    bf162 h, l;
                    split2(acc[im][jn][p * 2], h.x, l.x);
                    split2(acc[im][jn][p * 2 + 1], h.y, l.y);
                    *(bf162*)(g_ao_h + idx) = h;
                    *(bf162*)(g_ao_l + idx) = l;
                }
    } else {  // MODE 3
        float* sc = (float*)dynsm;  // 128 x 65 fp32 = 33 KB
        const int bB = m0 >> 10;
        const int s0 = m0 & 1023;
#pragma unroll
        for (int pass = 0; pass < 2; ++pass) {
            __syncthreads();
            if (wc == pass) {
#pragma unroll
                for (int im = 0; im < 2; ++im)
#pragma unroll
                    for (int jn = 0; jn < 8; ++jn)
#pragma unroll
                        for (int p = 0; p < 2; ++p) {
                            int rloc = wr * 32 + im * 16 + r0l + p * 8;
                            int cloc = jn * 8 + c0l;
                            sc[rloc * 65 + cloc] = acc[im][jn][p * 2];
                            sc[rloc * 65 + cloc + 1] = acc[im][jn][p * 2 + 1];
                        }
            }
            __syncthreads();
            int nl = tid >> 2;
            int sblk = (tid & 3) * 32;
            int n = n0 + pass * 64 + nl;
            size_t obase = (((size_t)(bB * CC + n)) << 10) + s0 + sblk;
            float bn = bias[n];
#pragma unroll
            for (int j = 0; j < 32; j += 4) {
                float4 xr = *(const float4*)(resid + obase + j);
                float4 o;
                o.x = sc[(sblk + j + 0) * 65 + nl] + bn + xr.x;
                o.y = sc[(sblk + j + 1) * 65 + nl] + bn + xr.y;
                o.z = sc[(sblk + j + 2) * 65 + nl] + bn + xr.z;
                o.w = sc[(sblk + j + 3) * 65 + nl] + bn + xr.w;
                *(float4*)(C + obase + j) = o;
            }
        }
    }
}

// ---------------------------------------------------------------------------
// Row softmax over 1024 cols: fp32 scores -> split bf16 P
// ---------------------------------------------------------------------------
__global__ __launch_bounds__(256) void softmax_kernel() {
    size_t row = blockIdx.x;
    const float* p = g_scores + (row << 10);
    int tid = threadIdx.x;
    float4 v = reinterpret_cast<const float4*>(p)[tid];

    float m = fmaxf(fmaxf(v.x, v.y), fmaxf(v.z, v.w));
#pragma unroll
    for (int o = 16; o; o >>= 1) m = fmaxf(m, __shfl_xor_sync(0xffffffffu, m, o));
    __shared__ float redm[8], reds[8];
    if ((tid & 31) == 0) redm[tid >> 5] = m;
    __syncthreads();
    m = redm[0];
#pragma unroll
    for (int w = 1; w < 8; ++w) m = fmaxf(m, redm[w]);

    v.x = __expf(v.x - m); v.y = __expf(v.y - m);
    v.z = __expf(v.z - m); v.w = __expf(v.w - m);
    float s = v.x + v.y + v.z + v.w;
#pragma unroll
    for (int o = 16; o; o >>= 1) s += __shfl_xor_sync(0xffffffffu, s, o);
    if ((tid & 31) == 0) reds[tid >> 5] = s;
    __syncthreads();
    s = reds[0];
#pragma unroll
    for (int w = 1; w < 8; ++w) s += reds[w];

    float inv = 1.0f / s;
    v.x *= inv; v.y *= inv; v.z *= inv; v.w *= inv;

    bf162 h0, l0, h1, l1;
    split2(v.x, h0.x, l0.x); split2(v.y, h0.y, l0.y);
    split2(v.z, h1.x, l1.x); split2(v.w, h1.y, l1.y);
    size_t ob = (row << 10) + tid * 4;
    *(bf162*)(g_p_h + ob) = h0; *(bf162*)(g_p_h + ob + 2) = h1;
    *(bf162*)(g_p_l + ob) = l0; *(bf162*)(g_p_l + ob + 2) = l1;
}

// ---------------------------------------------------------------------------
extern "C" void kernel_launch(void* const* d_in, const int* in_sizes, int n_in,
                              void* d_out, int out_size) {
    const float* x  = (const float*)d_in[0];
    const float* Wp = (const float*)d_in[1];
    const float* bp = (const float*)d_in[2];
    const float* Wo = (const float*)d_in[3];
    const float* bo = (const float*)d_in[4];
    float* out = (float*)d_out;

    bf16 *xt_h, *xt_l, *WpT_h, *WpT_l, *WoT_h, *WoT_l;
    bf16 *q_h, *q_l, *k_h, *k_l, *v_h, *v_l, *vt_h, *vt_l;
    bf16 *p_h, *p_l, *ao_h, *ao_l;
    float* sc;
    cudaGetSymbolAddress((void**)&xt_h, g_xt_h);
    cudaGetSymbolAddress((void**)&xt_l, g_xt_l);
    cudaGetSymbolAddress((void**)&WpT_h, g_WpT_h);
    cudaGetSymbolAddress((void**)&WpT_l, g_WpT_l);
    cudaGetSymbolAddress((void**)&WoT_h, g_WoT_h);
    cudaGetSymbolAddress((void**)&WoT_l, g_WoT_l);
    cudaGetSymbolAddress((void**)&q_h, g_q_h);
    cudaGetSymbolAddress((void**)&q_l, g_q_l);
    cudaGetSymbolAddress((void**)&k_h, g_k_h);
    cudaGetSymbolAddress((void**)&k_l, g_k_l);
    cudaGetSymbolAddress((void**)&v_h, g_v_h);
    cudaGetSymbolAddress((void**)&v_l, g_v_l);
    cudaGetSymbolAddress((void**)&vt_h, g_vt_h);
    cudaGetSymbolAddress((void**)&vt_l, g_vt_l);
    cudaGetSymbolAddress((void**)&p_h, g_p_h);
    cudaGetSymbolAddress((void**)&p_l, g_p_l);
    cudaGetSymbolAddress((void**)&ao_h, g_ao_h);
    cudaGetSymbolAddress((void**)&ao_l, g_ao_l);
    cudaGetSymbolAddress((void**)&sc, g_scores);

    cudaFuncSetAttribute(gemm_bf16x3<0>, cudaFuncAttributeMaxDynamicSharedMemorySize, SMEM_DYN);
    cudaFuncSetAttribute(gemm_bf16x3<1>, cudaFuncAttributeMaxDynamicSharedMemorySize, SMEM_DYN);
    cudaFuncSetAttribute(gemm_bf16x3<2>, cudaFuncAttributeMaxDynamicSharedMemorySize, SMEM_DYN);
    cudaFuncSetAttribute(gemm_bf16x3<3>, cudaFuncAttributeMaxDynamicSharedMemorySize, SMEM_DYN);

    dim3 tb(32, 8);
    // Split-convert + transpose inputs
    convT<<<dim3(SS / 32, CC / 32, BB), tb>>>(x, xt_h, xt_l, CC, SS);
    convT<<<dim3(QKVN / 32, CC / 32, 1), tb>>>(Wp, WpT_h, WpT_l, CC, QKVN);
    convT<<<dim3(CC / 32, HD / 32, 1), tb>>>(Wo, WoT_h, WoT_l, HD, CC);

    // QKV projection: [8192,256] @ [6144,256]^T
    gemm_bf16x3<0><<<dim3(QKVN / BN, (BB * SS) / BM, 1), 256, SMEM_DYN>>>(
        xt_h, xt_l, WpT_h, WpT_l, nullptr, nullptr, nullptr,
        CC, CC, CC, 0, 0, 0, 0, bp, nullptr, 1.0f);

    // V -> V^T per head (bf16 pairs)
    txpb2<<<dim3(DK / 32, SS / 32, BB * NH), tb>>>(v_h, v_l, vt_h, vt_l, SS, DK);

    // Q K^T (scaled)
    gemm_bf16x3<1><<<dim3(SS / BN, SS / BM, BB * NH), 256, SMEM_DYN>>>(
        q_h, q_l, k_h, k_l, sc, nullptr, nullptr,
        DK, DK, DK, SS, (size_t)SS * DK, (size_t)SS * DK, (size_t)SS * SS,
        nullptr, nullptr, 0.0625f);

    softmax_kernel<<<BB * NH * SS, 256>>>();

    // P V
    gemm_bf16x3<2><<<dim3(DK / BN, SS / BM, BB * NH), 256, SMEM_DYN>>>(
        p_h, p_l, vt_h, vt_l, nullptr, nullptr, nullptr,
        SS, SS, SS, 0, (size_t)SS * SS, (size_t)DK * SS, 0,
        nullptr, nullptr, 1.0f);

    // Out projection + bias + residual
    gemm_bf16x3<3><<<dim3(CC / BN, (BB * SS) / BM, 1), 256, SMEM_DYN>>>(
        ao_h, ao_l, WoT_h, WoT_l, out, nullptr, nullptr,
        HD, HD, HD, 0, 0, 0, 0, bo, x, 1.0f);
}

// round 5
// speedup vs baseline: 2.3976x; 2.3976x over previous
#include <cuda_runtime.h>
#include <cuda_fp16.h>
#include <cstdint>
#include <cstddef>

// ---------------------------------------------------------------------------
#define BB 8
#define CC 256
#define SS 1024
#define NH 8
#define DK 256
#define HD 2048
#define QKVN 6144

#define BM 128
#define BN 128
#define BKF 32                     // K elements per block
#define PAD 40                     // fp16 per smem row (80B; conflict-free)
#define TILEB (128 * PAD * 2)      // 10240 B per tile
#define STAGEB (2 * TILEB)         // A, B
#define NSTAGE 3
#define SMEM_DYN (NSTAGE * STAGEB) // 61440 B

typedef __half fp16;

// ---------------------------------------------------------------------------
// Device scratch (allocation-free)
// ---------------------------------------------------------------------------
__device__ __align__(128) fp16 g_xt[BB * SS * CC];        // [b*S+s][c]
__device__ __align__(128) fp16 g_WpT[QKVN * CC];          // [n][k]
__device__ __align__(128) fp16 g_WoT[CC * HD];            // [n][k]
__device__ __align__(128) fp16 g_q[BB * NH * SS * DK];    // [bh][s][d]
__device__ __align__(128) fp16 g_k[BB * NH * SS * DK];
__device__ __align__(128) fp16 g_v[BB * NH * SS * DK];
__device__ __align__(128) fp16 g_vt[BB * NH * DK * SS];   // [bh][d][s]
__device__ __align__(128) float g_scores[(size_t)BB * NH * SS * SS];
__device__ __align__(128) fp16 g_p[(size_t)BB * NH * SS * SS];
__device__ __align__(128) fp16 g_ao[BB * SS * HD];        // [b*S+s][h*DK+d]

// ---------------------------------------------------------------------------
// PTX helpers
// ---------------------------------------------------------------------------
__device__ __forceinline__ uint32_t smem_u32(const void* p) {
    uint32_t a;
    asm("{ .reg .u64 t; cvta.to.shared.u64 t, %1; cvt.u32.u64 %0, t; }"
        : "=r"(a) : "l"(p));
    return a;
}
__device__ __forceinline__ void cpa16(uint32_t dst, const void* src) {
    asm volatile("cp.async.cg.shared.global [%0], [%1], 16;"
                 :: "r"(dst), "l"(src) : "memory");
}
__device__ __forceinline__ void cpa_commit() {
    asm volatile("cp.async.commit_group;" ::: "memory");
}
template <int N> __device__ __forceinline__ void cpa_wait() {
    asm volatile("cp.async.wait_group %0;" :: "n"(N) : "memory");
}
__device__ __forceinline__ void ldsm4(uint32_t* r, uint32_t addr) {
    asm volatile("ldmatrix.sync.aligned.m8n8.x4.shared.b16 {%0,%1,%2,%3}, [%4];"
                 : "=r"(r[0]), "=r"(r[1]), "=r"(r[2]), "=r"(r[3]) : "r"(addr));
}
__device__ __forceinline__ void mma16816(float* d, const uint32_t* a,
                                         uint32_t b0, uint32_t b1) {
    asm volatile(
        "mma.sync.aligned.m16n8k16.row.col.f32.f16.f16.f32 "
        "{%0,%1,%2,%3}, {%4,%5,%6,%7}, {%8,%9}, {%0,%1,%2,%3};"
        : "+f"(d[0]), "+f"(d[1]), "+f"(d[2]), "+f"(d[3])
        : "r"(a[0]), "r"(a[1]), "r"(a[2]), "r"(a[3]), "r"(b0), "r"(b1));
}

// ---------------------------------------------------------------------------
// fp32 [Z][R][C] -> transposed fp16 [Z][C][R]
// ---------------------------------------------------------------------------
__global__ __launch_bounds__(256) void convT(const float* __restrict__ in,
                                             fp16* __restrict__ o, int R, int C) {
    __shared__ float t[32][33];
    int z = blockIdx.z;
    const float* I = in + (size_t)z * R * C;
    size_t ob = (size_t)z * R * C;
    int c0 = blockIdx.x * 32, r0 = blockIdx.y * 32;
    int x = threadIdx.x, y = threadIdx.y;
#pragma unroll
    for (int i = 0; i < 32; i += 8)
        t[y + i][x] = I[(size_t)(r0 + y + i) * C + c0 + x];
    __syncthreads();
#pragma unroll
    for (int i = 0; i < 32; i += 8)
        o[ob + (size_t)(c0 + y + i) * R + r0 + x] = __float2half(t[x][y + i]);
}

// ---------------------------------------------------------------------------
// fp16 transpose: [Z][R][C] -> [Z][C][R]
// ---------------------------------------------------------------------------
__global__ __launch_bounds__(256) void txph(const fp16* __restrict__ in,
                                            fp16* __restrict__ o, int R, int C) {
    __shared__ fp16 t[32][33];
    int z = blockIdx.z;
    size_t zb = (size_t)z * R * C;
    int c0 = blockIdx.x * 32, r0 = blockIdx.y * 32;
    int x = threadIdx.x, y = threadIdx.y;
#pragma unroll
    for (int i = 0; i < 32; i += 8)
        t[y + i][x] = in[zb + (size_t)(r0 + y + i) * C + c0 + x];
    __syncthreads();
#pragma unroll
    for (int i = 0; i < 32; i += 8)
        o[zb + (size_t)(c0 + y + i) * R + r0 + x] = t[x][y + i];
}

// ---------------------------------------------------------------------------
// fp16 GEMM, 3-stage cp.async, 1 sync/iter. C tile = A[128,K] * B[128,K]^T
// MODE 0: QKV -> bias, scatter fp16 q/k/v
// MODE 1: QK^T -> scale, fp32 scores
// MODE 2: PV -> fp16 attnout
// MODE 3: proj -> bias + residual + transposed fp32 store
// ---------------------------------------------------------------------------
template <int MODE>
__global__ __launch_bounds__(256, 2) void gemm_fp16(
    const fp16* __restrict__ A, const fp16* __restrict__ B,
    float* __restrict__ C, fp16* __restrict__ Cf,
    int K, int ldA, int ldB, int ldC, size_t Az, size_t Bz, size_t Cz,
    const float* __restrict__ bias, const float* __restrict__ resid, float scale) {
    extern __shared__ __align__(16) char dynsm[];
    const uint32_t sbase = smem_u32(dynsm);

    const int tid = threadIdx.x;
    const int wid = tid >> 5;
    const int lane = tid & 31;
    const int wr = wid >> 1;
    const int wc = wid & 1;

    const int z = blockIdx.z;
    const int m0 = blockIdx.y * BM;
    const int n0 = blockIdx.x * BN;
    const fp16* tA = A + Az * z + (size_t)m0 * ldA;
    const fp16* tB = B + Bz * z + (size_t)n0 * ldB;
    const int NKB = K / BKF;

    // loader: row = tid>>1, 32B chunk = tid&1 (each thread: 2x16B for A, 2x16B for B)
    const int crow = tid >> 1;
    const int ccol = (tid & 1) * 16;  // fp16 element offset (32B)

    auto issue = [&](int kb, int stg) {
        uint32_t sb = sbase + stg * STAGEB + (crow * PAD + ccol) * 2;
        const fp16* ga = tA + (size_t)crow * ldA + kb * BKF + ccol;
        cpa16(sb, ga);
        cpa16(sb + 16, ga + 8);
        const fp16* gb = tB + (size_t)crow * ldB + kb * BKF + ccol;
        cpa16(sb + TILEB, gb);
        cpa16(sb + TILEB + 16, gb + 8);
    };

    // ldmatrix per-lane offsets
    const int lr = lane & 15, lhf = lane >> 4;
    uint32_t aoff[2], boff[4];
#pragma unroll
    for (int im = 0; im < 2; ++im)
        aoff[im] = ((wr * 32 + im * 16 + lr) * PAD + lhf * 8) * 2;
#pragma unroll
    for (int jn = 0; jn < 4; ++jn)
        boff[jn] = ((wc * 64 + jn * 16 + lr) * PAD + lhf * 8) * 2;

    float acc[2][8][4] = {};

    issue(0, 0); cpa_commit();
    if (NKB > 1) { issue(1, 1); cpa_commit(); }

    for (int kb = 0; kb < NKB; ++kb) {
        if (kb + 2 < NKB) cpa_wait<1>();
        else cpa_wait<0>();
        __syncthreads();
        if (kb + 2 < NKB) { issue(kb + 2, (kb + 2) % NSTAGE); cpa_commit(); }

        const int stg = kb % NSTAGE;
        const uint32_t sA = sbase + stg * STAGEB;
        const uint32_t sB = sA + TILEB;

#pragma unroll
        for (int ks = 0; ks < 32; ks += 16) {
            const uint32_t kso = ks * 2;
            uint32_t af[2][4], bf[4][4];
            ldsm4(af[0], sA + aoff[0] + kso);
            ldsm4(af[1], sA + aoff[1] + kso);
#pragma unroll
            for (int jn = 0; jn < 4; ++jn) ldsm4(bf[jn], sB + boff[jn] + kso);
#pragma unroll
            for (int im = 0; im < 2; ++im)
#pragma unroll
                for (int jn = 0; jn < 4; ++jn) {
                    mma16816(acc[im][jn * 2], af[im], bf[jn][0], bf[jn][2]);
                    mma16816(acc[im][jn * 2 + 1], af[im], bf[jn][1], bf[jn][3]);
                }
        }
    }
    __syncthreads();

    // ---- epilogue ----
    const int r0l = lane >> 2;
    const int c0l = (lane & 3) * 2;

    if (MODE == 0) {
        const int hB = n0 / 768;
        const int loc0 = n0 % 768;
        const int seg = loc0 >> 8;
        const int d0 = loc0 & 255;
        fp16* dst = (seg == 0) ? g_q : (seg == 1) ? g_k : g_v;
#pragma unroll
        for (int im = 0; im < 2; ++im)
#pragma unroll
            for (int jn = 0; jn < 8; ++jn)
#pragma unroll
                for (int p = 0; p < 2; ++p) {
                    int m = m0 + wr * 32 + im * 16 + r0l + p * 8;
                    int nb = wc * 64 + jn * 8 + c0l;
                    int b = m >> 10, s2 = m & 1023;
                    size_t row = ((size_t)(b * NH + hB) * SS + s2) * DK + d0 + nb;
                    __half2 h;
                    h.x = __float2half(acc[im][jn][p * 2] + bias[n0 + nb]);
                    h.y = __float2half(acc[im][jn][p * 2 + 1] + bias[n0 + nb + 1]);
                    *(__half2*)(dst + row) = h;
                }
    } else if (MODE == 1) {
        float* Cb = C + Cz * z;
#pragma unroll
        for (int im = 0; im < 2; ++im)
#pragma unroll
            for (int jn = 0; jn < 8; ++jn)
#pragma unroll
                for (int p = 0; p < 2; ++p) {
                    int m = m0 + wr * 32 + im * 16 + r0l + p * 8;
                    int nb = wc * 64 + jn * 8 + c0l;
                    float2 o;
                    o.x = acc[im][jn][p * 2] * scale;
                    o.y = acc[im][jn][p * 2 + 1] * scale;
                    *(float2*)(Cb + (size_t)m * ldC + n0 + nb) = o;
                }
    } else if (MODE == 2) {
        int b = z >> 3, h2 = z & 7;
        size_t base = (size_t)b * SS * HD + h2 * DK;
#pragma unroll
        for (int im = 0; im < 2; ++im)
#pragma unroll
            for (int jn = 0; jn < 8; ++jn)
#pragma unroll
                for (int p = 0; p < 2; ++p) {
                    int m = m0 + wr * 32 + im * 16 + r0l + p * 8;
                    int nb = wc * 64 + jn * 8 + c0l;
                    size_t idx = base + (size_t)m * HD + n0 + nb;
                    __half2 h;
                    h.x = __float2half(acc[im][jn][p * 2]);
                    h.y = __float2half(acc[im][jn][p * 2 + 1]);
                    *(__half2*)(g_ao + idx) = h;
                }
    } else {  // MODE 3
        float* sc = (float*)dynsm;  // 128 x 65 fp32 = 33.3 KB (fits 60 KB)
        const int bB = m0 >> 10;
        const int s0 = m0 & 1023;
#pragma unroll
        for (int pass = 0; pass < 2; ++pass) {
            __syncthreads();
            if (wc == pass) {
#pragma unroll
                for (int im = 0; im < 2; ++im)
#pragma unroll
                    for (int jn = 0; jn < 8; ++jn)
#pragma unroll
                        for (int p = 0; p < 2; ++p) {
                            int rloc = wr * 32 + im * 16 + r0l + p * 8;
                            int cloc = jn * 8 + c0l;
                            sc[rloc * 65 + cloc] = acc[im][jn][p * 2];
                            sc[rloc * 65 + cloc + 1] = acc[im][jn][p * 2 + 1];
                        }
            }
            __syncthreads();
            int nl = tid >> 2;
            int sblk = (tid & 3) * 32;
            int n = n0 + pass * 64 + nl;
            size_t obase = (((size_t)(bB * CC + n)) << 10) + s0 + sblk;
            float bn = bias[n];
#pragma unroll
            for (int j = 0; j < 32; j += 4) {
                float4 xr = *(const float4*)(resid + obase + j);
                float4 o;
                o.x = sc[(sblk + j + 0) * 65 + nl] + bn + xr.x;
                o.y = sc[(sblk + j + 1) * 65 + nl] + bn + xr.y;
                o.z = sc[(sblk + j + 2) * 65 + nl] + bn + xr.z;
                o.w = sc[(sblk + j + 3) * 65 + nl] + bn + xr.w;
                *(float4*)(C + obase + j) = o;
            }
        }
    }
}

// ---------------------------------------------------------------------------
// Row softmax over 1024 cols: fp32 scores -> fp16 P
// ---------------------------------------------------------------------------
__global__ __launch_bounds__(256) void softmax_kernel() {
    size_t row = blockIdx.x;
    const float* p = g_scores + (row << 10);
    int tid = threadIdx.x;
    float4 v = reinterpret_cast<const float4*>(p)[tid];

    float m = fmaxf(fmaxf(v.x, v.y), fmaxf(v.z, v.w));
#pragma unroll
    for (int o = 16; o; o >>= 1) m = fmaxf(m, __shfl_xor_sync(0xffffffffu, m, o));
    __shared__ float redm[8], reds[8];
    if ((tid & 31) == 0) redm[tid >> 5] = m;
    __syncthreads();
    m = redm[0];
#pragma unroll
    for (int w = 1; w < 8; ++w) m = fmaxf(m, redm[w]);

    v.x = __expf(v.x - m); v.y = __expf(v.y - m);
    v.z = __expf(v.z - m); v.w = __expf(v.w - m);
    float s = v.x + v.y + v.z + v.w;
#pragma unroll
    for (int o = 16; o; o >>= 1) s += __shfl_xor_sync(0xffffffffu, s, o);
    if ((tid & 31) == 0) reds[tid >> 5] = s;
    __syncthreads();
    s = reds[0];
#pragma unroll
    for (int w = 1; w < 8; ++w) s += reds[w];

    float inv = 1.0f / s;
    __half2 h0, h1;
    h0.x = __float2half(v.x * inv); h0.y = __float2half(v.y * inv);
    h1.x = __float2half(v.z * inv); h1.y = __float2half(v.w * inv);
    size_t ob = (row << 10) + tid * 4;
    *(__half2*)(g_p + ob) = h0;
    *(__half2*)(g_p + ob + 2) = h1;
}

// ---------------------------------------------------------------------------
extern "C" void kernel_launch(void* const* d_in, const int* in_sizes, int n_in,
                              void* d_out, int out_size) {
    const float* x  = (const float*)d_in[0];
    const float* Wp = (const float*)d_in[1];
    const float* bp = (const float*)d_in[2];
    const float* Wo = (const float*)d_in[3];
    const float* bo = (const float*)d_in[4];
    float* out = (float*)d_out;

    fp16 *xt, *WpT, *WoT, *q, *k, *v, *vt, *pp, *ao;
    float* sc;
    cudaGetSymbolAddress((void**)&xt, g_xt);
    cudaGetSymbolAddress((void**)&WpT, g_WpT);
    cudaGetSymbolAddress((void**)&WoT, g_WoT);
    cudaGetSymbolAddress((void**)&q, g_q);
    cudaGetSymbolAddress((void**)&k, g_k);
    cudaGetSymbolAddress((void**)&v, g_v);
    cudaGetSymbolAddress((void**)&vt, g_vt);
    cudaGetSymbolAddress((void**)&pp, g_p);
    cudaGetSymbolAddress((void**)&ao, g_ao);
    cudaGetSymbolAddress((void**)&sc, g_scores);

    cudaFuncSetAttribute(gemm_fp16<0>, cudaFuncAttributeMaxDynamicSharedMemorySize, SMEM_DYN);
    cudaFuncSetAttribute(gemm_fp16<1>, cudaFuncAttributeMaxDynamicSharedMemorySize, SMEM_DYN);
    cudaFuncSetAttribute(gemm_fp16<2>, cudaFuncAttributeMaxDynamicSharedMemorySize, SMEM_DYN);
    cudaFuncSetAttribute(gemm_fp16<3>, cudaFuncAttributeMaxDynamicSharedMemorySize, SMEM_DYN);

    dim3 tb(32, 8);
    convT<<<dim3(SS / 32, CC / 32, BB), tb>>>(x, xt, CC, SS);
    convT<<<dim3(QKVN / 32, CC / 32, 1), tb>>>(Wp, WpT, CC, QKVN);
    convT<<<dim3(CC / 32, HD / 32, 1), tb>>>(Wo, WoT, HD, CC);

    // QKV projection: [8192,256] @ [6144,256]^T
    gemm_fp16<0><<<dim3(QKVN / BN, (BB * SS) / BM, 1), 256, SMEM_DYN>>>(
        xt, WpT, nullptr, nullptr, CC, CC, CC, 0, 0, 0, 0, bp, nullptr, 1.0f);

    // V -> V^T per head
    txph<<<dim3(DK / 32, SS / 32, BB * NH), tb>>>(v, vt, SS, DK);

    // Q K^T (scaled)
    gemm_fp16<1><<<dim3(SS / BN, SS / BM, BB * NH), 256, SMEM_DYN>>>(
        q, k, sc, nullptr, DK, DK, DK, SS,
        (size_t)SS * DK, (size_t)SS * DK, (size_t)SS * SS, nullptr, nullptr, 0.0625f);

    softmax_kernel<<<BB * NH * SS, 256>>>();

    // P V
    gemm_fp16<2><<<dim3(DK / BN, SS / BM, BB * NH), 256, SMEM_DYN>>>(
        pp, vt, nullptr, nullptr, SS, SS, SS, 0,
        (size_t)SS * SS, (size_t)DK * SS, 0, nullptr, nullptr, 1.0f);

    // Out projection + bias + residual
    gemm_fp16<3><<<dim3(CC / BN, (BB * SS) / BM, 1), 256, SMEM_DYN>>>(
        ao, WoT, out, nullptr, HD, HD, HD, 0, 0, 0, 0, bo, x, 1.0f);
}

// round 6
// speedup vs baseline: 2.4152x; 1.0074x over previous
#include <cuda_runtime.h>
#include <cuda_fp16.h>
#include <cstdint>
#include <cstddef>

// ---------------------------------------------------------------------------
#define BB 8
#define CC 256
#define SS 1024
#define NH 8
#define DK 256
#define HD 2048
#define QKVN 6144

#define BM 128
#define BN 128
#define BKF 32                     // K elements per block
#define PAD 40                     // fp16 per smem row (80B; ldsm conflict-free)
#define TILEB (128 * PAD * 2)      // 10240 B per tile
#define STAGEB (2 * TILEB)         // A, B
#define NSTAGE 4
#define SMEM_DYN (NSTAGE * STAGEB) // 81920 B

typedef __half fp16;

// ---------------------------------------------------------------------------
// Device scratch (allocation-free)
// ---------------------------------------------------------------------------
__device__ __align__(128) fp16 g_xt[BB * SS * CC];        // [b*S+s][c]
__device__ __align__(128) fp16 g_WpT[QKVN * CC];          // [n][k]
__device__ __align__(128) fp16 g_WoT[CC * HD];            // [n][k]
__device__ __align__(128) fp16 g_q[BB * NH * SS * DK];    // [bh][s][d]
__device__ __align__(128) fp16 g_k[BB * NH * SS * DK];
__device__ __align__(128) fp16 g_v[BB * NH * SS * DK];
__device__ __align__(128) fp16 g_vt[BB * NH * DK * SS];   // [bh][d][s]
__device__ __align__(128) float g_scores[(size_t)BB * NH * SS * SS];
__device__ __align__(128) fp16 g_p[(size_t)BB * NH * SS * SS];
__device__ __align__(128) fp16 g_ao[BB * SS * HD];        // [b*S+s][h*DK+d]

// ---------------------------------------------------------------------------
// PTX helpers
// ---------------------------------------------------------------------------
__device__ __forceinline__ uint32_t smem_u32(const void* p) {
    uint32_t a;
    asm("{ .reg .u64 t; cvta.to.shared.u64 t, %1; cvt.u32.u64 %0, t; }"
        : "=r"(a) : "l"(p));
    return a;
}
__device__ __forceinline__ void cpa16(uint32_t dst, const void* src) {
    asm volatile("cp.async.cg.shared.global [%0], [%1], 16;"
                 :: "r"(dst), "l"(src) : "memory");
}
__device__ __forceinline__ void cpa_commit() {
    asm volatile("cp.async.commit_group;" ::: "memory");
}
template <int N> __device__ __forceinline__ void cpa_wait() {
    asm volatile("cp.async.wait_group %0;" :: "n"(N) : "memory");
}
__device__ __forceinline__ void ldsm4(uint32_t* r, uint32_t addr) {
    asm volatile("ldmatrix.sync.aligned.m8n8.x4.shared.b16 {%0,%1,%2,%3}, [%4];"
                 : "=r"(r[0]), "=r"(r[1]), "=r"(r[2]), "=r"(r[3]) : "r"(addr));
}
__device__ __forceinline__ void mma16816(float* d, const uint32_t* a,
                                         uint32_t b0, uint32_t b1) {
    asm volatile(
        "mma.sync.aligned.m16n8k16.row.col.f32.f16.f16.f32 "
        "{%0,%1,%2,%3}, {%4,%5,%6,%7}, {%8,%9}, {%0,%1,%2,%3};"
        : "+f"(d[0]), "+f"(d[1]), "+f"(d[2]), "+f"(d[3])
        : "r"(a[0]), "r"(a[1]), "r"(a[2]), "r"(a[3]), "r"(b0), "r"(b1));
}

// ---------------------------------------------------------------------------
// fp32 [Z][R][C] -> transposed fp16 [Z][C][R]
// ---------------------------------------------------------------------------
__global__ __launch_bounds__(256) void convT(const float* __restrict__ in,
                                             fp16* __restrict__ o, int R, int C) {
    __shared__ float t[32][33];
    int z = blockIdx.z;
    const float* I = in + (size_t)z * R * C;
    size_t ob = (size_t)z * R * C;
    int c0 = blockIdx.x * 32, r0 = blockIdx.y * 32;
    int x = threadIdx.x, y = threadIdx.y;
#pragma unroll
    for (int i = 0; i < 32; i += 8)
        t[y + i][x] = I[(size_t)(r0 + y + i) * C + c0 + x];
    __syncthreads();
#pragma unroll
    for (int i = 0; i < 32; i += 8)
        o[ob + (size_t)(c0 + y + i) * R + r0 + x] = __float2half(t[x][y + i]);
}

// ---------------------------------------------------------------------------
// fp16 transpose: [Z][R][C] -> [Z][C][R]
// ---------------------------------------------------------------------------
__global__ __launch_bounds__(256) void txph(const fp16* __restrict__ in,
                                            fp16* __restrict__ o, int R, int C) {
    __shared__ fp16 t[32][33];
    int z = blockIdx.z;
    size_t zb = (size_t)z * R * C;
    int c0 = blockIdx.x * 32, r0 = blockIdx.y * 32;
    int x = threadIdx.x, y = threadIdx.y;
#pragma unroll
    for (int i = 0; i < 32; i += 8)
        t[y + i][x] = in[zb + (size_t)(r0 + y + i) * C + c0 + x];
    __syncthreads();
#pragma unroll
    for (int i = 0; i < 32; i += 8)
        o[zb + (size_t)(c0 + y + i) * R + r0 + x] = t[x][y + i];
}

// ---------------------------------------------------------------------------
// fp16 GEMM, 4-stage cp.async, hoisted frags, 1 sync/iter.
// C tile = A[128,K] * B[128,K]^T
// MODE 0: QKV -> bias, scatter fp16 q/k/v
// MODE 1: QK^T -> scale, fp32 scores
// MODE 2: PV -> fp16 attnout
// MODE 3: proj -> bias + residual + transposed fp32 store
// ---------------------------------------------------------------------------
template <int MODE>
__global__ __launch_bounds__(256, 2) void gemm_fp16(
    const fp16* __restrict__ A, const fp16* __restrict__ B,
    float* __restrict__ C, fp16* __restrict__ Cf,
    int K, int ldA, int ldB, int ldC, size_t Az, size_t Bz, size_t Cz,
    const float* __restrict__ bias, const float* __restrict__ resid, float scale) {
    extern __shared__ __align__(16) char dynsm[];
    const uint32_t sbase = smem_u32(dynsm);

    const int tid = threadIdx.x;
    const int wid = tid >> 5;
    const int lane = tid & 31;
    const int wr = wid >> 1;
    const int wc = wid & 1;

    const int z = blockIdx.z;
    const int m0 = blockIdx.y * BM;
    const int n0 = blockIdx.x * BN;
    const fp16* tA = A + Az * z + (size_t)m0 * ldA;
    const fp16* tB = B + Bz * z + (size_t)n0 * ldB;
    const int NKB = K / BKF;

    // loader: row = tid>>1, 32B chunk = tid&1
    const int crow = tid >> 1;
    const int ccol = (tid & 1) * 16;

    auto issue = [&](int kb, int stg) {
        uint32_t sb = sbase + stg * STAGEB + (crow * PAD + ccol) * 2;
        const fp16* ga = tA + (size_t)crow * ldA + kb * BKF + ccol;
        cpa16(sb, ga);
        cpa16(sb + 16, ga + 8);
        const fp16* gb = tB + (size_t)crow * ldB + kb * BKF + ccol;
        cpa16(sb + TILEB, gb);
        cpa16(sb + TILEB + 16, gb + 8);
    };

    // ldmatrix per-lane offsets
    const int lr = lane & 15, lhf = lane >> 4;
    uint32_t aoff[2], boff[4];
#pragma unroll
    for (int im = 0; im < 2; ++im)
        aoff[im] = ((wr * 32 + im * 16 + lr) * PAD + lhf * 8) * 2;
#pragma unroll
    for (int jn = 0; jn < 4; ++jn)
        boff[jn] = ((wc * 64 + jn * 16 + lr) * PAD + lhf * 8) * 2;

    float acc[2][8][4] = {};

    issue(0, 0); cpa_commit();
    if (NKB > 1) { issue(1, 1); cpa_commit(); }
    if (NKB > 2) { issue(2, 2); cpa_commit(); }

    for (int kb = 0; kb < NKB; ++kb) {
        if (kb + 3 <= NKB) cpa_wait<2>();
        else if (kb + 2 == NKB) cpa_wait<1>();
        else cpa_wait<0>();
        __syncthreads();
        if (kb + 3 < NKB) { issue(kb + 3, (kb + 3) % NSTAGE); cpa_commit(); }

        const int stg = kb % NSTAGE;
        const uint32_t sA = sbase + stg * STAGEB;
        const uint32_t sB = sA + TILEB;

        // hoist ALL frag loads for both k-steps, then run all MMAs
        uint32_t af[2][2][4], bf[2][4][4];
#pragma unroll
        for (int ks = 0; ks < 2; ++ks) {
            const uint32_t kso = ks * 32;
            ldsm4(af[ks][0], sA + aoff[0] + kso);
            ldsm4(af[ks][1], sA + aoff[1] + kso);
#pragma unroll
            for (int jn = 0; jn < 4; ++jn) ldsm4(bf[ks][jn], sB + boff[jn] + kso);
        }
#pragma unroll
        for (int ks = 0; ks < 2; ++ks)
#pragma unroll
            for (int im = 0; im < 2; ++im)
#pragma unroll
                for (int jn = 0; jn < 4; ++jn) {
                    mma16816(acc[im][jn * 2], af[ks][im], bf[ks][jn][0], bf[ks][jn][2]);
                    mma16816(acc[im][jn * 2 + 1], af[ks][im], bf[ks][jn][1], bf[ks][jn][3]);
                }
    }
    __syncthreads();

    // ---- epilogue ----
    const int r0l = lane >> 2;
    const int c0l = (lane & 3) * 2;

    if (MODE == 0) {
        const int hB = n0 / 768;
        const int loc0 = n0 % 768;
        const int seg = loc0 >> 8;
        const int d0 = loc0 & 255;
        fp16* dst = (seg == 0) ? g_q : (seg == 1) ? g_k : g_v;
#pragma unroll
        for (int im = 0; im < 2; ++im)
#pragma unroll
            for (int jn = 0; jn < 8; ++jn)
#pragma unroll
                for (int p = 0; p < 2; ++p) {
                    int m = m0 + wr * 32 + im * 16 + r0l + p * 8;
                    int nb = wc * 64 + jn * 8 + c0l;
                    int b = m >> 10, s2 = m & 1023;
                    size_t row = ((size_t)(b * NH + hB) * SS + s2) * DK + d0 + nb;
                    __half2 h;
                    h.x = __float2half(acc[im][jn][p * 2] + bias[n0 + nb]);
                    h.y = __float2half(acc[im][jn][p * 2 + 1] + bias[n0 + nb + 1]);
                    *(__half2*)(dst + row) = h;
                }
    } else if (MODE == 1) {
        float* Cb = C + Cz * z;
#pragma unroll
        for (int im = 0; im < 2; ++im)
#pragma unroll
            for (int jn = 0; jn < 8; ++jn)
#pragma unroll
                for (int p = 0; p < 2; ++p) {
                    int m = m0 + wr * 32 + im * 16 + r0l + p * 8;
                    int nb = wc * 64 + jn * 8 + c0l;
                    float2 o;
                    o.x = acc[im][jn][p * 2] * scale;
                    o.y = acc[im][jn][p * 2 + 1] * scale;
                    *(float2*)(Cb + (size_t)m * ldC + n0 + nb) = o;
                }
    } else if (MODE == 2) {
        int b = z >> 3, h2 = z & 7;
        size_t base = (size_t)b * SS * HD + h2 * DK;
#pragma unroll
        for (int im = 0; im < 2; ++im)
#pragma unroll
            for (int jn = 0; jn < 8; ++jn)
#pragma unroll
                for (int p = 0; p < 2; ++p) {
                    int m = m0 + wr * 32 + im * 16 + r0l + p * 8;
                    int nb = wc * 64 + jn * 8 + c0l;
                    size_t idx = base + (size_t)m * HD + n0 + nb;
                    __half2 h;
                    h.x = __float2half(acc[im][jn][p * 2]);
                    h.y = __float2half(acc[im][jn][p * 2 + 1]);
                    *(__half2*)(g_ao + idx) = h;
                }
    } else {  // MODE 3
        float* sc = (float*)dynsm;  // 128 x 65 fp32 = 33.3 KB (fits 80 KB)
        const int bB = m0 >> 10;
        const int s0 = m0 & 1023;
#pragma unroll
        for (int pass = 0; pass < 2; ++pass) {
            __syncthreads();
            if (wc == pass) {
#pragma unroll
                for (int im = 0; im < 2; ++im)
#pragma unroll
                    for (int jn = 0; jn < 8; ++jn)
#pragma unroll
                        for (int p = 0; p < 2; ++p) {
                            int rloc = wr * 32 + im * 16 + r0l + p * 8;
                            int cloc = jn * 8 + c0l;
                            sc[rloc * 65 + cloc] = acc[im][jn][p * 2];
                            sc[rloc * 65 + cloc + 1] = acc[im][jn][p * 2 + 1];
                        }
            }
            __syncthreads();
            int nl = tid >> 2;
            int sblk = (tid & 3) * 32;
            int n = n0 + pass * 64 + nl;
            size_t obase = (((size_t)(bB * CC + n)) << 10) + s0 + sblk;
            float bn = bias[n];
#pragma unroll
            for (int j = 0; j < 32; j += 4) {
                float4 xr = *(const float4*)(resid + obase + j);
                float4 o;
                o.x = sc[(sblk + j + 0) * 65 + nl] + bn + xr.x;
                o.y = sc[(sblk + j + 1) * 65 + nl] + bn + xr.y;
                o.z = sc[(sblk + j + 2) * 65 + nl] + bn + xr.z;
                o.w = sc[(sblk + j + 3) * 65 + nl] + bn + xr.w;
                *(float4*)(C + obase + j) = o;
            }
        }
    }
}

// ---------------------------------------------------------------------------
// Row softmax over 1024 cols: fp32 scores -> fp16 P
// ---------------------------------------------------------------------------
__global__ __launch_bounds__(256) void softmax_kernel() {
    size_t row = blockIdx.x;
    const float* p = g_scores + (row << 10);
    int tid = threadIdx.x;
    float4 v = reinterpret_cast<const float4*>(p)[tid];

    float m = fmaxf(fmaxf(v.x, v.y), fmaxf(v.z, v.w));
#pragma unroll
    for (int o = 16; o; o >>= 1) m = fmaxf(m, __shfl_xor_sync(0xffffffffu, m, o));
    __shared__ float redm[8], reds[8];
    if ((tid & 31) == 0) redm[tid >> 5] = m;
    __syncthreads();
    m = redm[0];
#pragma unroll
    for (int w = 1; w < 8; ++w) m = fmaxf(m, redm[w]);

    v.x = __expf(v.x - m); v.y = __expf(v.y - m);
    v.z = __expf(v.z - m); v.w = __expf(v.w - m);
    float s = v.x + v.y + v.z + v.w;
#pragma unroll
    for (int o = 16; o; o >>= 1) s += __shfl_xor_sync(0xffffffffu, s, o);
    if ((tid & 31) == 0) reds[tid >> 5] = s;
    __syncthreads();
    s = reds[0];
#pragma unroll
    for (int w = 1; w < 8; ++w) s += reds[w];

    float inv = 1.0f / s;
    __half2 h0, h1;
    h0.x = __float2half(v.x * inv); h0.y = __float2half(v.y * inv);
    h1.x = __float2half(v.z * inv); h1.y = __float2half(v.w * inv);
    size_t ob = (row << 10) + tid * 4;
    *(__half2*)(g_p + ob) = h0;
    *(__half2*)(g_p + ob + 2) = h1;
}

// ---------------------------------------------------------------------------
extern "C" void kernel_launch(void* const* d_in, const int* in_sizes, int n_in,
                              void* d_out, int out_size) {
    const float* x  = (const float*)d_in[0];
    const float* Wp = (const float*)d_in[1];
    const float* bp = (const float*)d_in[2];
    const float* Wo = (const float*)d_in[3];
    const float* bo = (const float*)d_in[4];
    float* out = (float*)d_out;

    fp16 *xt, *WpT, *WoT, *q, *k, *v, *vt, *pp, *ao;
    float* sc;
    cudaGetSymbolAddress((void**)&xt, g_xt);
    cudaGetSymbolAddress((void**)&WpT, g_WpT);
    cudaGetSymbolAddress((void**)&WoT, g_WoT);
    cudaGetSymbolAddress((void**)&q, g_q);
    cudaGetSymbolAddress((void**)&k, g_k);
    cudaGetSymbolAddress((void**)&v, g_v);
    cudaGetSymbolAddress((void**)&vt, g_vt);
    cudaGetSymbolAddress((void**)&pp, g_p);
    cudaGetSymbolAddress((void**)&ao, g_ao);
    cudaGetSymbolAddress((void**)&sc, g_scores);

    cudaFuncSetAttribute(gemm_fp16<0>, cudaFuncAttributeMaxDynamicSharedMemorySize, SMEM_DYN);
    cudaFuncSetAttribute(gemm_fp16<1>, cudaFuncAttributeMaxDynamicSharedMemorySize, SMEM_DYN);
    cudaFuncSetAttribute(gemm_fp16<2>, cudaFuncAttributeMaxDynamicSharedMemorySize, SMEM_DYN);
    cudaFuncSetAttribute(gemm_fp16<3>, cudaFuncAttributeMaxDynamicSharedMemorySize, SMEM_DYN);

    dim3 tb(32, 8);
    convT<<<dim3(SS / 32, CC / 32, BB), tb>>>(x, xt, CC, SS);
    convT<<<dim3(QKVN / 32, CC / 32, 1), tb>>>(Wp, WpT, CC, QKVN);
    convT<<<dim3(CC / 32, HD / 32, 1), tb>>>(Wo, WoT, HD, CC);

    // QKV projection: [8192,256] @ [6144,256]^T
    gemm_fp16<0><<<dim3(QKVN / BN, (BB * SS) / BM, 1), 256, SMEM_DYN>>>(
        xt, WpT, nullptr, nullptr, CC, CC, CC, 0, 0, 0, 0, bp, nullptr, 1.0f);

    // V -> V^T per head
    txph<<<dim3(DK / 32, SS / 32, BB * NH), tb>>>(v, vt, SS, DK);

    // Q K^T (scaled)
    gemm_fp16<1><<<dim3(SS / BN, SS / BM, BB * NH), 256, SMEM_DYN>>>(
        q, k, sc, nullptr, DK, DK, DK, SS,
        (size_t)SS * DK, (size_t)SS * DK, (size_t)SS * SS, nullptr, nullptr, 0.0625f);

    softmax_kernel<<<BB * NH * SS, 256>>>();

    // P V
    gemm_fp16<2><<<dim3(DK / BN, SS / BM, BB * NH), 256, SMEM_DYN>>>(
        pp, vt, nullptr, nullptr, SS, SS, SS, 0,
        (size_t)SS * SS, (size_t)DK * SS, 0, nullptr, nullptr, 1.0f);

    // Out projection + bias + residual
    gemm_fp16<3><<<dim3(CC / BN, (BB * SS) / BM, 1), 256, SMEM_DYN>>>(
        ao, WoT, out, nullptr, HD, HD, HD, 0, 0, 0, 0, bo, x, 1.0f);
}